// round 3
// baseline (speedup 1.0000x reference)
#include <cuda_runtime.h>

#define SEQ    2048
#define DMODEL 2048
#define NHEADS 32
#define DHEAD  64

typedef unsigned long long u64;

// Packed fp32x2 ops (Blackwell FFMA2 path — only reachable via PTX)
#define FMA2(d, a, b) \
    asm("fma.rn.f32x2 %0, %1, %2, %0;" : "+l"(d) : "l"(a), "l"(b))
#define MUL2(d, a, b) \
    asm("mul.rn.f32x2 %0, %1, %2;" : "=l"(d) : "l"(a), "l"(b))
#define PACK_DUP(d, x) \
    asm("mov.b64 %0, {%1, %1};" : "=l"(d) : "f"(x))
#define UNPACK2(lo, hi, v) \
    asm("mov.b64 {%0, %1}, %2;" : "=f"(lo), "=f"(hi) : "l"(v))

// Scratch (allocation-free rule: __device__ globals)
__device__ float g_Q[SEQ * DMODEL];
__device__ float g_K[SEQ * DMODEL];
__device__ float g_V[SEQ * DMODEL];
__device__ float g_Qh[SEQ * DMODEL];   // [h][l][d] layout, Q pre-scaled
__device__ float g_Kh[SEQ * DMODEL];
__device__ float g_Vh[SEQ * DMODEL];
__device__ float g_ctx[SEQ * DMODEL];  // attention output in [l][d*32+h] layout

// ---------------------------------------------------------------------------
// NT SGEMM via FFMA2: C[M,N] = A[M,K] @ W[N,K]^T + bias[N], 2048^3 row-major.
// 128x128 block tile, BK=8, 8x8 per-thread microtile (packed 8x4 f32x2), 256 thr.
// ---------------------------------------------------------------------------
__device__ __forceinline__ void gemm_nt_body(
    const float* __restrict__ A, const float* __restrict__ W,
    const float* __restrict__ bias, float* __restrict__ C)
{
    __shared__ float As[8][128];
    __shared__ float Bs[8][128];

    const int t    = threadIdx.x;
    const int tx   = t & 15;
    const int ty   = t >> 4;
    const int row0 = blockIdx.y * 128;
    const int col0 = blockIdx.x * 128;
    const int lrow = t >> 1;         // 0..127
    const int lk   = (t & 1) * 4;    // 0 or 4

    u64 acc2[8][4];                  // [i][j-pair], packed along N
#pragma unroll
    for (int i = 0; i < 8; i++)
#pragma unroll
        for (int j = 0; j < 4; j++) acc2[i][j] = 0ull;

    for (int k0 = 0; k0 < DMODEL; k0 += 8) {
        float4 av = *(const float4*)&A[(row0 + lrow) * DMODEL + k0 + lk];
        float4 bv = *(const float4*)&W[(col0 + lrow) * DMODEL + k0 + lk];
        As[lk + 0][lrow] = av.x; As[lk + 1][lrow] = av.y;
        As[lk + 2][lrow] = av.z; As[lk + 3][lrow] = av.w;
        Bs[lk + 0][lrow] = bv.x; Bs[lk + 1][lrow] = bv.y;
        Bs[lk + 2][lrow] = bv.z; Bs[lk + 3][lrow] = bv.w;
        __syncthreads();
#pragma unroll
        for (int kk = 0; kk < 8; kk++) {
            float ar[8];
            *(float4*)&ar[0] = *(const float4*)&As[kk][ty * 8];
            *(float4*)&ar[4] = *(const float4*)&As[kk][ty * 8 + 4];
            // B fragment directly as 64-bit pairs (16B-aligned smem)
            ulonglong2 b01 = *(const ulonglong2*)&Bs[kk][tx * 8];
            ulonglong2 b23 = *(const ulonglong2*)&Bs[kk][tx * 8 + 4];
            u64 b2[4] = { b01.x, b01.y, b23.x, b23.y };
            u64 a2[8];
#pragma unroll
            for (int i = 0; i < 8; i++) PACK_DUP(a2[i], ar[i]);
#pragma unroll
            for (int i = 0; i < 8; i++)
#pragma unroll
                for (int j = 0; j < 4; j++)
                    FMA2(acc2[i][j], a2[i], b2[j]);
        }
        __syncthreads();
    }

    float bb[8];
#pragma unroll
    for (int j = 0; j < 8; j++) bb[j] = bias[col0 + tx * 8 + j];
#pragma unroll
    for (int i = 0; i < 8; i++) {
        float c[8];
#pragma unroll
        for (int j = 0; j < 4; j++) {
            float lo, hi;
            UNPACK2(lo, hi, acc2[i][j]);
            c[2 * j]     = lo + bb[2 * j];
            c[2 * j + 1] = hi + bb[2 * j + 1];
        }
        float* cp = &C[(row0 + ty * 8 + i) * DMODEL + col0 + tx * 8];
        *(float4*)&cp[0] = *(float4*)&c[0];
        *(float4*)&cp[4] = *(float4*)&c[4];
    }
}

__global__ void __launch_bounds__(256, 2) qkv_gemm_kernel(
    const float* __restrict__ X,
    const float* __restrict__ Wq, const float* __restrict__ bq,
    const float* __restrict__ Wk, const float* __restrict__ bk,
    const float* __restrict__ Wv, const float* __restrict__ bv)
{
    const float* W; const float* b; float* C;
    if (blockIdx.z == 0)      { W = Wq; b = bq; C = g_Q; }
    else if (blockIdx.z == 1) { W = Wk; b = bk; C = g_K; }
    else                      { W = Wv; b = bv; C = g_V; }
    gemm_nt_body(X, W, b, C);
}

__global__ void __launch_bounds__(256, 2) out_gemm_kernel(
    const float* __restrict__ Wo, const float* __restrict__ bo,
    float* __restrict__ out)
{
    gemm_nt_body(g_ctx, Wo, bo, out);
}

// ---------------------------------------------------------------------------
// Head transpose: [l][d*32+h] -> [h][l][d] (d contiguous), coalesced both ways
// via padded smem. Q pre-scaled by 1/sqrt(D_MODEL).
// ---------------------------------------------------------------------------
__global__ void __launch_bounds__(256) head_transpose_kernel()
{
    const float* src; float* dst; float scale;
    if (blockIdx.y == 0)      { src = g_Q; dst = g_Qh; scale = rsqrtf((float)DMODEL); }
    else if (blockIdx.y == 1) { src = g_K; dst = g_Kh; scale = 1.f; }
    else                      { src = g_V; dst = g_Vh; scale = 1.f; }

    __shared__ float s[4 * 2080];   // [l][h][d]: l*2080 + h*65 + d
    const int t  = threadIdx.x;
    const int l0 = blockIdx.x * 4;

#pragma unroll
    for (int i = 0; i < 8; i++) {
        int f4 = t + 256 * i;             // 0..2047 float4s (4 rows x 512)
        int l  = f4 >> 9;
        int n  = (f4 & 511) * 4;
        float4 v = *(const float4*)&src[(l0 + l) * DMODEL + n];
        s[l * 2080 + ((n + 0) & 31) * 65 + ((n + 0) >> 5)] = v.x * scale;
        s[l * 2080 + ((n + 1) & 31) * 65 + ((n + 1) >> 5)] = v.y * scale;
        s[l * 2080 + ((n + 2) & 31) * 65 + ((n + 2) >> 5)] = v.z * scale;
        s[l * 2080 + ((n + 3) & 31) * 65 + ((n + 3) >> 5)] = v.w * scale;
    }
    __syncthreads();

#pragma unroll
    for (int i = 0; i < 8; i++) {
        int f4 = t + 256 * i;             // flat over h(32) x l(4) x d4(16)
        int d  = (f4 & 15) * 4;
        int l  = (f4 >> 4) & 3;
        int hh = f4 >> 6;
        int base = l * 2080 + hh * 65 + d;
        float4 v;
        v.x = s[base + 0]; v.y = s[base + 1];
        v.z = s[base + 2]; v.w = s[base + 3];
        *(float4*)&dst[hh * (SEQ * DHEAD) + (l0 + l) * DHEAD + d] = v;
    }
}

// ---------------------------------------------------------------------------
// Flash attention, fp32 with FFMA2 inner loops.
// One block = (head, 64-query tile); streams 32-key tiles. 256 threads.
// ---------------------------------------------------------------------------
__global__ void __launch_bounds__(256) attn_kernel()
{
    const int h  = blockIdx.y;
    const int q0 = blockIdx.x * 64;
    const float* __restrict__ Qh = g_Qh + h * (SEQ * DHEAD);
    const float* __restrict__ Kh = g_Kh + h * (SEQ * DHEAD);
    const float* __restrict__ Vh = g_Vh + h * (SEQ * DHEAD);

    __shared__ float Qs[64][68];
    __shared__ float Ks[32][68];
    __shared__ float Vs[32][68];
    __shared__ float Ss[64][36];
    __shared__ float alpha_s[64];
    __shared__ float ls[64];

    const int t  = threadIdx.x;
    const int tx = t & 15;
    const int ty = t >> 4;

    // Load Q tile 64x64 (coalesced)
#pragma unroll
    for (int i = 0; i < 4; i++) {
        int f4 = t + 256 * i;            // 0..1023
        int r  = f4 >> 4;
        int d  = (f4 & 15) * 4;
        *(float4*)&Qs[r][d] = *(const float4*)&Qh[(q0 + r) * DHEAD + d];
    }

    float m_r = -1e30f, l_r = 0.f;       // softmax-role row = t>>2
    u64 O2[4][2];                        // [i][d-pair], packed along head dim
#pragma unroll
    for (int i = 0; i < 4; i++) { O2[i][0] = 0ull; O2[i][1] = 0ull; }

    for (int kt = 0; kt < SEQ / 32; kt++) {
        const int k0 = kt * 32;
#pragma unroll
        for (int i = 0; i < 2; i++) {
            int f4 = t + 256 * i;        // 0..511
            int r  = f4 >> 4;
            int d  = (f4 & 15) * 4;
            *(float4*)&Ks[r][d] = *(const float4*)&Kh[(k0 + r) * DHEAD + d];
            *(float4*)&Vs[r][d] = *(const float4*)&Vh[(k0 + r) * DHEAD + d];
        }
        __syncthreads();

        // S = Q K^T via FFMA2, paired along k (even/odd partial sums)
        u64 sacc2[4][2];
#pragma unroll
        for (int i = 0; i < 4; i++) { sacc2[i][0] = 0ull; sacc2[i][1] = 0ull; }
#pragma unroll
        for (int k = 0; k < 64; k += 4) {
            ulonglong2 q2[4], kv2[2];
#pragma unroll
            for (int i = 0; i < 4; i++) q2[i]  = *(const ulonglong2*)&Qs[ty * 4 + i][k];
#pragma unroll
            for (int j = 0; j < 2; j++) kv2[j] = *(const ulonglong2*)&Ks[tx * 2 + j][k];
#pragma unroll
            for (int i = 0; i < 4; i++)
#pragma unroll
                for (int j = 0; j < 2; j++) {
                    FMA2(sacc2[i][j], q2[i].x, kv2[j].x);
                    FMA2(sacc2[i][j], q2[i].y, kv2[j].y);
                }
        }
#pragma unroll
        for (int i = 0; i < 4; i++)
#pragma unroll
            for (int j = 0; j < 2; j++) {
                float lo, hi;
                UNPACK2(lo, hi, sacc2[i][j]);
                Ss[ty * 4 + i][tx * 2 + j] = lo + hi;
            }
        __syncthreads();

        // Online softmax: row r = t>>2, 8 cols per thread
        {
            const int r  = t >> 2;
            const int c0 = (t & 3) * 8;
            float sv[8];
            float lm = -1e30f;
#pragma unroll
            for (int j = 0; j < 8; j++) { sv[j] = Ss[r][c0 + j]; lm = fmaxf(lm, sv[j]); }
            lm = fmaxf(lm, __shfl_xor_sync(0xffffffffu, lm, 1));
            lm = fmaxf(lm, __shfl_xor_sync(0xffffffffu, lm, 2));
            float mnew  = fmaxf(m_r, lm);
            float alpha = __expf(m_r - mnew);
            float sum = 0.f;
#pragma unroll
            for (int j = 0; j < 8; j++) {
                float p = __expf(sv[j] - mnew);
                Ss[r][c0 + j] = p;
                sum += p;
            }
            sum += __shfl_xor_sync(0xffffffffu, sum, 1);
            sum += __shfl_xor_sync(0xffffffffu, sum, 2);
            l_r = l_r * alpha + sum;
            m_r = mnew;
            if ((t & 3) == 0) { alpha_s[r] = alpha; ls[r] = l_r; }
        }
        __syncthreads();

        // O rescale + PV via FFMA2: rows ty*4..+3, dims tx*4..+3 (2 pairs)
#pragma unroll
        for (int i = 0; i < 4; i++) {
            u64 a2;
            PACK_DUP(a2, alpha_s[ty * 4 + i]);
            MUL2(O2[i][0], O2[i][0], a2);
            MUL2(O2[i][1], O2[i][1], a2);
        }
#pragma unroll
        for (int c = 0; c < 32; c++) {
            ulonglong2 vv = *(const ulonglong2*)&Vs[c][tx * 4];
#pragma unroll
            for (int i = 0; i < 4; i++) {
                u64 p2;
                PACK_DUP(p2, Ss[ty * 4 + i][c]);
                FMA2(O2[i][0], p2, vv.x);
                FMA2(O2[i][1], p2, vv.y);
            }
        }
        __syncthreads();   // protect Ks/Vs/Ss before next iteration's loads
    }

    // Write ctx[(q0+r)][d*32+h], d = tx*4 + {0..3}
#pragma unroll
    for (int i = 0; i < 4; i++) {
        const int r = ty * 4 + i;
        const float inv = 1.f / ls[r];
        float o[4];
        UNPACK2(o[0], o[1], O2[i][0]);
        UNPACK2(o[2], o[3], O2[i][1]);
#pragma unroll
        for (int j = 0; j < 4; j++) {
            g_ctx[(q0 + r) * DMODEL + (tx * 4 + j) * NHEADS + h] = o[j] * inv;
        }
    }
}

// ---------------------------------------------------------------------------
extern "C" void kernel_launch(void* const* d_in, const int* in_sizes, int n_in,
                              void* d_out, int out_size)
{
    (void)in_sizes; (void)n_in; (void)out_size;
    const float* X  = (const float*)d_in[0];
    const float* Wq = (const float*)d_in[1];
    const float* bq = (const float*)d_in[2];
    const float* Wk = (const float*)d_in[3];
    const float* bk = (const float*)d_in[4];
    const float* Wv = (const float*)d_in[5];
    const float* bv = (const float*)d_in[6];
    const float* Wo = (const float*)d_in[7];
    const float* bo = (const float*)d_in[8];
    float* out = (float*)d_out;

    qkv_gemm_kernel<<<dim3(16, 16, 3), 256>>>(X, Wq, bq, Wk, bk, Wv, bv);
    head_transpose_kernel<<<dim3(SEQ / 4, 3), 256>>>();
    attn_kernel<<<dim3(SEQ / 64, NHEADS), 256>>>();
    out_gemm_kernel<<<dim3(16, 16), 256>>>(Wo, bo, out);
}

// round 7
// speedup vs baseline: 1.3671x; 1.3671x over previous
#include <cuda_runtime.h>
#include <cuda_bf16.h>
#include <cstdint>

#define SEQ    2048
#define DMODEL 2048
#define NHEADS 32
#define DHEAD  64

// ===========================================================================
// Scratch (allocation-free rule: __device__ globals)
// ===========================================================================
__device__ float g_Q[SEQ * DMODEL];
__device__ float g_K[SEQ * DMODEL];
__device__ float g_V[SEQ * DMODEL];
__device__ float g_Qh[SEQ * DMODEL];
__device__ float g_Kh[SEQ * DMODEL];
__device__ float g_Vh[SEQ * DMODEL];
__device__ float g_ctx[SEQ * DMODEL];

__device__ __nv_bfloat16 g_Xhi[SEQ * DMODEL],     g_Xlo[SEQ * DMODEL];
__device__ __nv_bfloat16 g_Wqhi[DMODEL * DMODEL], g_Wqlo[DMODEL * DMODEL];
__device__ __nv_bfloat16 g_Wkhi[DMODEL * DMODEL], g_Wklo[DMODEL * DMODEL];
__device__ __nv_bfloat16 g_Wvhi[DMODEL * DMODEL], g_Wvlo[DMODEL * DMODEL];
__device__ __nv_bfloat16 g_Wohi[DMODEL * DMODEL], g_Wolo[DMODEL * DMODEL];
__device__ __nv_bfloat16 g_ctxhi[SEQ * DMODEL],   g_ctxlo[SEQ * DMODEL];

__device__ __forceinline__ uint32_t smem_to_u32(const void* p) {
    uint32_t a;
    asm("{ .reg .u64 t; cvta.to.shared.u64 t, %1; cvt.u32.u64 %0, t; }"
        : "=r"(a) : "l"(p));
    return a;
}

#define MMA_BF16(d, a, b) \
    asm volatile("mma.sync.aligned.m16n8k16.row.col.f32.bf16.bf16.f32 " \
        "{%0,%1,%2,%3}, {%4,%5,%6,%7}, {%8,%9}, {%0,%1,%2,%3};" \
        : "+f"((d)[0]), "+f"((d)[1]), "+f"((d)[2]), "+f"((d)[3]) \
        : "r"((a)[0]), "r"((a)[1]), "r"((a)[2]), "r"((a)[3]), \
          "r"((b)[0]), "r"((b)[1]))

#define CP_ASYNC16(sa, gp) \
    asm volatile("cp.async.cg.shared.global [%0], [%1], 16;" \
                 :: "r"(sa), "l"(gp) : "memory")
#define CP_COMMIT()  asm volatile("cp.async.commit_group;" ::: "memory")
#define CP_WAIT(n)   asm volatile("cp.async.wait_group %0;" :: "n"(n) : "memory")

// ===========================================================================
// fp32 -> (hi, lo) bf16 split.  which: 0=X 1=Wq 2=Wk 3=Wv 4=Wo 5=ctx
// ===========================================================================
__global__ void __launch_bounds__(256) split_kernel(const float* __restrict__ src, int which)
{
    __nv_bfloat16* hi; __nv_bfloat16* lo;
    switch (which) {
        case 0: hi = g_Xhi;  lo = g_Xlo;  break;
        case 1: hi = g_Wqhi; lo = g_Wqlo; break;
        case 2: hi = g_Wkhi; lo = g_Wklo; break;
        case 3: hi = g_Wvhi; lo = g_Wvlo; break;
        case 4: hi = g_Wohi; lo = g_Wolo; break;
        default: hi = g_ctxhi; lo = g_ctxlo; src = g_ctx; break;
    }
    int i = (blockIdx.x * 256 + threadIdx.x) * 4;
    float4 v = *(const float4*)&src[i];
    __nv_bfloat16 h0 = __float2bfloat16_rn(v.x);
    __nv_bfloat16 h1 = __float2bfloat16_rn(v.y);
    __nv_bfloat16 h2 = __float2bfloat16_rn(v.z);
    __nv_bfloat16 h3 = __float2bfloat16_rn(v.w);
    __nv_bfloat16 l0 = __float2bfloat16_rn(v.x - __bfloat162float(h0));
    __nv_bfloat16 l1 = __float2bfloat16_rn(v.y - __bfloat162float(h1));
    __nv_bfloat16 l2 = __float2bfloat16_rn(v.z - __bfloat162float(h2));
    __nv_bfloat16 l3 = __float2bfloat16_rn(v.w - __bfloat162float(h3));
    ushort4 hv, lv;
    hv.x = __bfloat16_as_ushort(h0); hv.y = __bfloat16_as_ushort(h1);
    hv.z = __bfloat16_as_ushort(h2); hv.w = __bfloat16_as_ushort(h3);
    lv.x = __bfloat16_as_ushort(l0); lv.y = __bfloat16_as_ushort(l1);
    lv.z = __bfloat16_as_ushort(l2); lv.w = __bfloat16_as_ushort(l3);
    *(ushort4*)&hi[i] = hv;
    *(ushort4*)&lo[i] = lv;
}

// ===========================================================================
// bf16-split NT GEMM via mma.sync (HMMA): C = A @ B^T + bias, 2048^3.
// 128x128 CTA tile, 8 warps (warp tile 64x32), BK=16, cp.async double-buffer.
// Per K-16 step: 16 mma x 3 split combos (Ah*Bh + Ah*Bl + Al*Bh).
// smem: [stage][tile(Ah,Al,Bh,Bl)][128][24] bf16 = 49152 B total
//       (stride 24 -> 16B-aligned rows, conflict-free frag loads;
//        48KB fits the DEFAULT dynamic-smem limit: no cudaFuncSetAttribute)
// ===========================================================================
#define GSTRIDE   24
#define TILE_E    (128 * GSTRIDE)      // 3072 elems per tile
#define STAGE_E   (4 * TILE_E)         // 12288 elems per stage
#define GEMM_SMEM (2 * STAGE_E * 2)    // 49152 bytes

__device__ __forceinline__ void bf16s_gemm_body(
    const __nv_bfloat16* __restrict__ Ahi, const __nv_bfloat16* __restrict__ Alo,
    const __nv_bfloat16* __restrict__ Bhi, const __nv_bfloat16* __restrict__ Blo,
    const float* __restrict__ bias, float* __restrict__ C)
{
    extern __shared__ __nv_bfloat16 sm[];
    const uint32_t smb = smem_to_u32(sm);

    const int t    = threadIdx.x;
    const int warp = t >> 5;
    const int lane = t & 31;
    const int g    = lane >> 2;
    const int tg   = lane & 3;
    const int wm   = warp & 1;    // 2 M-slots of 64
    const int wn   = warp >> 1;   // 4 N-slots of 32
    const int row0 = blockIdx.y * 128;
    const int col0 = blockIdx.x * 128;

    float d[4][4][4];
#pragma unroll
    for (int i = 0; i < 4; i++)
#pragma unroll
        for (int j = 0; j < 4; j++)
#pragma unroll
            for (int r = 0; r < 4; r++) d[i][j][r] = 0.f;

    // ---- prefetch stage 0 (kc = 0) ----
#pragma unroll
    for (int i = 0; i < 4; i++) {
        int cid  = t + 256 * i;          // 0..1023 chunks of 16B
        int tile = cid >> 8;
        int idx  = cid & 255;
        int r    = idx >> 1;
        int c    = idx & 1;              // 2 x 16B chunks per row
        const __nv_bfloat16* gp;
        if (tile == 0)      gp = &Ahi[(size_t)(row0 + r) * DMODEL + c * 8];
        else if (tile == 1) gp = &Alo[(size_t)(row0 + r) * DMODEL + c * 8];
        else if (tile == 2) gp = &Bhi[(size_t)(col0 + r) * DMODEL + c * 8];
        else                gp = &Blo[(size_t)(col0 + r) * DMODEL + c * 8];
        uint32_t sa = smb + (uint32_t)(tile * TILE_E + r * GSTRIDE + c * 8) * 2u;
        CP_ASYNC16(sa, gp);
    }
    CP_COMMIT();

    int s = 0;
    for (int kc = 0; kc < 128; kc++) {
        if (kc + 1 < 128) {
            // ---- prefetch next stage ----
            const int k0 = (kc + 1) * 16;
            const int sn = s ^ 1;
#pragma unroll
            for (int i = 0; i < 4; i++) {
                int cid  = t + 256 * i;
                int tile = cid >> 8;
                int idx  = cid & 255;
                int r    = idx >> 1;
                int c    = idx & 1;
                const __nv_bfloat16* gp;
                if (tile == 0)      gp = &Ahi[(size_t)(row0 + r) * DMODEL + k0 + c * 8];
                else if (tile == 1) gp = &Alo[(size_t)(row0 + r) * DMODEL + k0 + c * 8];
                else if (tile == 2) gp = &Bhi[(size_t)(col0 + r) * DMODEL + k0 + c * 8];
                else                gp = &Blo[(size_t)(col0 + r) * DMODEL + k0 + c * 8];
                uint32_t sa = smb + (uint32_t)(sn * STAGE_E + tile * TILE_E
                                               + r * GSTRIDE + c * 8) * 2u;
                CP_ASYNC16(sa, gp);
            }
            CP_COMMIT();
            CP_WAIT(1);
        } else {
            CP_WAIT(0);
        }
        __syncthreads();

        // ---- compute on stage s ----
        {
            const __nv_bfloat16* SAh = sm + s * STAGE_E;
            const __nv_bfloat16* SAl = SAh + TILE_E;
            const __nv_bfloat16* SBh = SAh + 2 * TILE_E;
            const __nv_bfloat16* SBl = SAh + 3 * TILE_E;
            uint32_t ah[4][4], al[4][4], bh[4][2], bl[4][2];
#pragma unroll
            for (int i = 0; i < 4; i++) {
                int off = (wm * 64 + i * 16 + g) * GSTRIDE + 2 * tg;
                ah[i][0] = *(const uint32_t*)(SAh + off);
                ah[i][1] = *(const uint32_t*)(SAh + off + 8 * GSTRIDE);
                ah[i][2] = *(const uint32_t*)(SAh + off + 8);
                ah[i][3] = *(const uint32_t*)(SAh + off + 8 * GSTRIDE + 8);
                al[i][0] = *(const uint32_t*)(SAl + off);
                al[i][1] = *(const uint32_t*)(SAl + off + 8 * GSTRIDE);
                al[i][2] = *(const uint32_t*)(SAl + off + 8);
                al[i][3] = *(const uint32_t*)(SAl + off + 8 * GSTRIDE + 8);
            }
#pragma unroll
            for (int j = 0; j < 4; j++) {
                int off = (wn * 32 + j * 8 + g) * GSTRIDE + 2 * tg;
                bh[j][0] = *(const uint32_t*)(SBh + off);
                bh[j][1] = *(const uint32_t*)(SBh + off + 8);
                bl[j][0] = *(const uint32_t*)(SBl + off);
                bl[j][1] = *(const uint32_t*)(SBl + off + 8);
            }
#pragma unroll
            for (int i = 0; i < 4; i++)
#pragma unroll
                for (int j = 0; j < 4; j++) {
                    MMA_BF16(d[i][j], ah[i], bh[j]);
                    MMA_BF16(d[i][j], ah[i], bl[j]);
                    MMA_BF16(d[i][j], al[i], bh[j]);
                }
        }
        __syncthreads();
        s ^= 1;
    }

    // Epilogue
#pragma unroll
    for (int j = 0; j < 4; j++) {
        const int col = col0 + wn * 32 + j * 8 + 2 * tg;
        const float b0 = bias[col], b1 = bias[col + 1];
#pragma unroll
        for (int i = 0; i < 4; i++) {
            const int ra = row0 + wm * 64 + i * 16 + g;
            float2 v0 = make_float2(d[i][j][0] + b0, d[i][j][1] + b1);
            float2 v1 = make_float2(d[i][j][2] + b0, d[i][j][3] + b1);
            *(float2*)&C[(size_t)ra * DMODEL + col]       = v0;
            *(float2*)&C[(size_t)(ra + 8) * DMODEL + col] = v1;
        }
    }
}

__global__ void __launch_bounds__(256, 1) qkv_bf16_gemm_kernel(
    const float* __restrict__ bq, const float* __restrict__ bk,
    const float* __restrict__ bv)
{
    if (blockIdx.z == 0)
        bf16s_gemm_body(g_Xhi, g_Xlo, g_Wqhi, g_Wqlo, bq, g_Q);
    else if (blockIdx.z == 1)
        bf16s_gemm_body(g_Xhi, g_Xlo, g_Wkhi, g_Wklo, bk, g_K);
    else
        bf16s_gemm_body(g_Xhi, g_Xlo, g_Wvhi, g_Wvlo, bv, g_V);
}

__global__ void __launch_bounds__(256, 1) o_bf16_gemm_kernel(
    const float* __restrict__ bo, float* __restrict__ out)
{
    bf16s_gemm_body(g_ctxhi, g_ctxlo, g_Wohi, g_Wolo, bo, out);
}

// ===========================================================================
// Head transpose: [l][d*32+h] -> [h][l][d]; Q pre-scaled by 1/sqrt(D_MODEL).
// ===========================================================================
__global__ void __launch_bounds__(256) head_transpose_kernel()
{
    const float* src; float* dst; float scale;
    if (blockIdx.y == 0)      { src = g_Q; dst = g_Qh; scale = rsqrtf((float)DMODEL); }
    else if (blockIdx.y == 1) { src = g_K; dst = g_Kh; scale = 1.f; }
    else                      { src = g_V; dst = g_Vh; scale = 1.f; }

    __shared__ float s[4 * 2080];   // [l][h][d]: l*2080 + h*65 + d
    const int t  = threadIdx.x;
    const int l0 = blockIdx.x * 4;

#pragma unroll
    for (int i = 0; i < 8; i++) {
        int f4 = t + 256 * i;
        int l  = f4 >> 9;
        int n  = (f4 & 511) * 4;
        float4 v = *(const float4*)&src[(l0 + l) * DMODEL + n];
        s[l * 2080 + ((n + 0) & 31) * 65 + ((n + 0) >> 5)] = v.x * scale;
        s[l * 2080 + ((n + 1) & 31) * 65 + ((n + 1) >> 5)] = v.y * scale;
        s[l * 2080 + ((n + 2) & 31) * 65 + ((n + 2) >> 5)] = v.z * scale;
        s[l * 2080 + ((n + 3) & 31) * 65 + ((n + 3) >> 5)] = v.w * scale;
    }
    __syncthreads();

#pragma unroll
    for (int i = 0; i < 8; i++) {
        int f4 = t + 256 * i;
        int d  = (f4 & 15) * 4;
        int l  = (f4 >> 4) & 3;
        int hh = f4 >> 6;
        int base = l * 2080 + hh * 65 + d;
        float4 v;
        v.x = s[base + 0]; v.y = s[base + 1];
        v.z = s[base + 2]; v.w = s[base + 3];
        *(float4*)&dst[hh * (SEQ * DHEAD) + (l0 + l) * DHEAD + d] = v;
    }
}

// ===========================================================================
// Flash attention, fp32 scalar (known-good R2 version).
// ===========================================================================
__global__ void __launch_bounds__(256) attn_kernel()
{
    const int h  = blockIdx.y;
    const int q0 = blockIdx.x * 64;
    const float* __restrict__ Qh = g_Qh + h * (SEQ * DHEAD);
    const float* __restrict__ Kh = g_Kh + h * (SEQ * DHEAD);
    const float* __restrict__ Vh = g_Vh + h * (SEQ * DHEAD);

    __shared__ float Qs[64][68];
    __shared__ float Ks[32][68];
    __shared__ float Vs[32][68];
    __shared__ float Ss[64][36];
    __shared__ float alpha_s[64];
    __shared__ float ls[64];

    const int t  = threadIdx.x;
    const int tx = t & 15;
    const int ty = t >> 4;

#pragma unroll
    for (int i = 0; i < 4; i++) {
        int f4 = t + 256 * i;
        int r  = f4 >> 4;
        int d  = (f4 & 15) * 4;
        *(float4*)&Qs[r][d] = *(const float4*)&Qh[(q0 + r) * DHEAD + d];
    }

    float m_r = -1e30f, l_r = 0.f;
    float Oacc[4][4];
#pragma unroll
    for (int i = 0; i < 4; i++)
#pragma unroll
        for (int j = 0; j < 4; j++) Oacc[i][j] = 0.f;

    for (int kt = 0; kt < SEQ / 32; kt++) {
        const int k0 = kt * 32;
#pragma unroll
        for (int i = 0; i < 2; i++) {
            int f4 = t + 256 * i;
            int r  = f4 >> 4;
            int d  = (f4 & 15) * 4;
            *(float4*)&Ks[r][d] = *(const float4*)&Kh[(k0 + r) * DHEAD + d];
            *(float4*)&Vs[r][d] = *(const float4*)&Vh[(k0 + r) * DHEAD + d];
        }
        __syncthreads();

        float sacc[4][2];
#pragma unroll
        for (int i = 0; i < 4; i++) { sacc[i][0] = 0.f; sacc[i][1] = 0.f; }
#pragma unroll
        for (int k = 0; k < 64; k += 4) {
            float4 q[4], kv[2];
#pragma unroll
            for (int i = 0; i < 4; i++) q[i]  = *(const float4*)&Qs[ty * 4 + i][k];
#pragma unroll
            for (int j = 0; j < 2; j++) kv[j] = *(const float4*)&Ks[tx * 2 + j][k];
#pragma unroll
            for (int i = 0; i < 4; i++)
#pragma unroll
                for (int j = 0; j < 2; j++)
                    sacc[i][j] += q[i].x * kv[j].x + q[i].y * kv[j].y
                                + q[i].z * kv[j].z + q[i].w * kv[j].w;
        }
#pragma unroll
        for (int i = 0; i < 4; i++) {
            Ss[ty * 4 + i][tx * 2 + 0] = sacc[i][0];
            Ss[ty * 4 + i][tx * 2 + 1] = sacc[i][1];
        }
        __syncthreads();

        {
            const int r  = t >> 2;
            const int c0 = (t & 3) * 8;
            float sv[8];
            float lm = -1e30f;
#pragma unroll
            for (int j = 0; j < 8; j++) { sv[j] = Ss[r][c0 + j]; lm = fmaxf(lm, sv[j]); }
            lm = fmaxf(lm, __shfl_xor_sync(0xffffffffu, lm, 1));
            lm = fmaxf(lm, __shfl_xor_sync(0xffffffffu, lm, 2));
            float mnew  = fmaxf(m_r, lm);
            float alpha = __expf(m_r - mnew);
            float sum = 0.f;
#pragma unroll
            for (int j = 0; j < 8; j++) {
                float p = __expf(sv[j] - mnew);
                Ss[r][c0 + j] = p;
                sum += p;
            }
            sum += __shfl_xor_sync(0xffffffffu, sum, 1);
            sum += __shfl_xor_sync(0xffffffffu, sum, 2);
            l_r = l_r * alpha + sum;
            m_r = mnew;
            if ((t & 3) == 0) { alpha_s[r] = alpha; ls[r] = l_r; }
        }
        __syncthreads();

#pragma unroll
        for (int i = 0; i < 4; i++) {
            float a = alpha_s[ty * 4 + i];
#pragma unroll
            for (int j = 0; j < 4; j++) Oacc[i][j] *= a;
        }
#pragma unroll
        for (int c = 0; c < 32; c++) {
            float4 vv = *(const float4*)&Vs[c][tx * 4];
#pragma unroll
            for (int i = 0; i < 4; i++) {
                float p = Ss[ty * 4 + i][c];
                Oacc[i][0] += p * vv.x;
                Oacc[i][1] += p * vv.y;
                Oacc[i][2] += p * vv.z;
                Oacc[i][3] += p * vv.w;
            }
        }
        __syncthreads();
    }

#pragma unroll
    for (int i = 0; i < 4; i++) {
        const int r = ty * 4 + i;
        const float inv = 1.f / ls[r];
#pragma unroll
        for (int j = 0; j < 4; j++) {
            g_ctx[(q0 + r) * DMODEL + (tx * 4 + j) * NHEADS + h] = Oacc[i][j] * inv;
        }
    }
}

// ===========================================================================
extern "C" void kernel_launch(void* const* d_in, const int* in_sizes, int n_in,
                              void* d_out, int out_size)
{
    (void)in_sizes; (void)n_in; (void)out_size;
    const float* X  = (const float*)d_in[0];
    const float* Wq = (const float*)d_in[1];
    const float* bq = (const float*)d_in[2];
    const float* Wk = (const float*)d_in[3];
    const float* bk = (const float*)d_in[4];
    const float* Wv = (const float*)d_in[5];
    const float* bv = (const float*)d_in[6];
    const float* Wo = (const float*)d_in[7];
    const float* bo = (const float*)d_in[8];
    float* out = (float*)d_out;

    const int SPLIT_GRID = (SEQ * DMODEL / 4) / 256;  // 4096
    split_kernel<<<SPLIT_GRID, 256>>>(X,  0);
    split_kernel<<<SPLIT_GRID, 256>>>(Wq, 1);
    split_kernel<<<SPLIT_GRID, 256>>>(Wk, 2);
    split_kernel<<<SPLIT_GRID, 256>>>(Wv, 3);
    split_kernel<<<SPLIT_GRID, 256>>>(Wo, 4);

    qkv_bf16_gemm_kernel<<<dim3(16, 16, 3), 256, GEMM_SMEM>>>(bq, bk, bv);
    head_transpose_kernel<<<dim3(SEQ / 4, 3), 256>>>();
    attn_kernel<<<dim3(SEQ / 64, NHEADS), 256>>>();
    split_kernel<<<SPLIT_GRID, 256>>>(nullptr, 5);
    o_bf16_gemm_kernel<<<dim3(16, 16), 256, GEMM_SMEM>>>(bo, out);
}

// round 12
// speedup vs baseline: 2.1663x; 1.5846x over previous
#include <cuda_runtime.h>
#include <cuda_bf16.h>
#include <cuda_fp16.h>
#include <cstdint>

#define SEQ    2048
#define DMODEL 2048
#define NHEADS 32
#define DHEAD  64
#define LOG2E  1.4426950408889634f

// ===========================================================================
// Scratch (allocation-free rule: __device__ globals)
// ===========================================================================
__device__ float g_Q[SEQ * DMODEL];
__device__ float g_K[SEQ * DMODEL];
__device__ float g_V[SEQ * DMODEL];
__device__ float g_Vh[SEQ * DMODEL];      // [h][l][d] fp32 (staging for vtrans)
__device__ float g_ctx[SEQ * DMODEL];

__device__ __half g_Qf16[SEQ * DMODEL];   // [h][l][d], pre-scaled by 1/sqrt(dm)
__device__ __half g_Kf16[SEQ * DMODEL];   // [h][l][d]
__device__ __half g_Vthi[SEQ * DMODEL];   // [h][d][l] hi
__device__ __half g_Vtlo[SEQ * DMODEL];   // [h][d][l] lo

__device__ __nv_bfloat16 g_Xhi[SEQ * DMODEL],     g_Xlo[SEQ * DMODEL];
__device__ __nv_bfloat16 g_Wqhi[DMODEL * DMODEL], g_Wqlo[DMODEL * DMODEL];
__device__ __nv_bfloat16 g_Wkhi[DMODEL * DMODEL], g_Wklo[DMODEL * DMODEL];
__device__ __nv_bfloat16 g_Wvhi[DMODEL * DMODEL], g_Wvlo[DMODEL * DMODEL];
__device__ __nv_bfloat16 g_Wohi[DMODEL * DMODEL], g_Wolo[DMODEL * DMODEL];
__device__ __nv_bfloat16 g_ctxhi[SEQ * DMODEL],   g_ctxlo[SEQ * DMODEL];

__device__ __forceinline__ uint32_t smem_to_u32(const void* p) {
    uint32_t a;
    asm("{ .reg .u64 t; cvta.to.shared.u64 t, %1; cvt.u32.u64 %0, t; }"
        : "=r"(a) : "l"(p));
    return a;
}

// fp32 exp2 on the FMA pipe: 2^x = 2^n * poly(f), n=rint(x), f in [-0.5,0.5].
// Degree-5 Taylor, rel err <= 3.4e-6. Valid for x <= 0 (clamped at -200).
__device__ __forceinline__ float exp2_poly(float x) {
    x = fmaxf(x, -200.f);
    float n = rintf(x);
    float f = x - n;
    float p = 1.3333558e-3f;
    p = fmaf(p, f, 9.6181291e-3f);
    p = fmaf(p, f, 5.5504109e-2f);
    p = fmaf(p, f, 2.4022651e-1f);
    p = fmaf(p, f, 6.9314718e-1f);
    p = fmaf(p, f, 1.0f);
    int e = (int)n;
    e = (e < -126) ? -126 : e;
    return p * __int_as_float((uint32_t)(e + 127) << 23);
}

#define MMA_BF16(d, a, b) \
    asm volatile("mma.sync.aligned.m16n8k16.row.col.f32.bf16.bf16.f32 " \
        "{%0,%1,%2,%3}, {%4,%5,%6,%7}, {%8,%9}, {%0,%1,%2,%3};" \
        : "+f"((d)[0]), "+f"((d)[1]), "+f"((d)[2]), "+f"((d)[3]) \
        : "r"((a)[0]), "r"((a)[1]), "r"((a)[2]), "r"((a)[3]), \
          "r"((b)[0]), "r"((b)[1]))

#define MMA_F16(d, a, b) \
    asm volatile("mma.sync.aligned.m16n8k16.row.col.f32.f16.f16.f32 " \
        "{%0,%1,%2,%3}, {%4,%5,%6,%7}, {%8,%9}, {%0,%1,%2,%3};" \
        : "+f"((d)[0]), "+f"((d)[1]), "+f"((d)[2]), "+f"((d)[3]) \
        : "r"((a)[0]), "r"((a)[1]), "r"((a)[2]), "r"((a)[3]), \
          "r"((b)[0]), "r"((b)[1]))

#define CP_ASYNC16(sa, gp) \
    asm volatile("cp.async.cg.shared.global [%0], [%1], 16;" \
                 :: "r"(sa), "l"(gp) : "memory")
#define CP_COMMIT()  asm volatile("cp.async.commit_group;" ::: "memory")
#define CP_WAIT(n)   asm volatile("cp.async.wait_group %0;" :: "n"(n) : "memory")

// ===========================================================================
// fp32 -> (hi, lo) bf16 split.  which: 0=X 1=Wq 2=Wk 3=Wv 4=Wo 5=ctx
// ===========================================================================
__global__ void __launch_bounds__(256) split_kernel(const float* __restrict__ src, int which)
{
    __nv_bfloat16* hi; __nv_bfloat16* lo;
    switch (which) {
        case 0: hi = g_Xhi;  lo = g_Xlo;  break;
        case 1: hi = g_Wqhi; lo = g_Wqlo; break;
        case 2: hi = g_Wkhi; lo = g_Wklo; break;
        case 3: hi = g_Wvhi; lo = g_Wvlo; break;
        case 4: hi = g_Wohi; lo = g_Wolo; break;
        default: hi = g_ctxhi; lo = g_ctxlo; src = g_ctx; break;
    }
    int i = (blockIdx.x * 256 + threadIdx.x) * 4;
    float4 v = *(const float4*)&src[i];
    __nv_bfloat16 h0 = __float2bfloat16_rn(v.x);
    __nv_bfloat16 h1 = __float2bfloat16_rn(v.y);
    __nv_bfloat16 h2 = __float2bfloat16_rn(v.z);
    __nv_bfloat16 h3 = __float2bfloat16_rn(v.w);
    __nv_bfloat16 l0 = __float2bfloat16_rn(v.x - __bfloat162float(h0));
    __nv_bfloat16 l1 = __float2bfloat16_rn(v.y - __bfloat162float(h1));
    __nv_bfloat16 l2 = __float2bfloat16_rn(v.z - __bfloat162float(h2));
    __nv_bfloat16 l3 = __float2bfloat16_rn(v.w - __bfloat162float(h3));
    ushort4 hv, lv;
    hv.x = __bfloat16_as_ushort(h0); hv.y = __bfloat16_as_ushort(h1);
    hv.z = __bfloat16_as_ushort(h2); hv.w = __bfloat16_as_ushort(h3);
    lv.x = __bfloat16_as_ushort(l0); lv.y = __bfloat16_as_ushort(l1);
    lv.z = __bfloat16_as_ushort(l2); lv.w = __bfloat16_as_ushort(l3);
    *(ushort4*)&hi[i] = hv;
    *(ushort4*)&lo[i] = lv;
}

// ===========================================================================
// bf16-split NT GEMM via mma.sync (R7, proven): C = A @ B^T + bias, 2048^3.
// ===========================================================================
#define GSTRIDE   24
#define TILE_E    (128 * GSTRIDE)
#define STAGE_E   (4 * TILE_E)
#define GEMM_SMEM (2 * STAGE_E * 2)    // 49152 bytes

__device__ __forceinline__ void bf16s_gemm_body(
    const __nv_bfloat16* __restrict__ Ahi, const __nv_bfloat16* __restrict__ Alo,
    const __nv_bfloat16* __restrict__ Bhi, const __nv_bfloat16* __restrict__ Blo,
    const float* __restrict__ bias, float* __restrict__ C)
{
    extern __shared__ __nv_bfloat16 sm[];
    const uint32_t smb = smem_to_u32(sm);

    const int t    = threadIdx.x;
    const int warp = t >> 5;
    const int lane = t & 31;
    const int g    = lane >> 2;
    const int tg   = lane & 3;
    const int wm   = warp & 1;
    const int wn   = warp >> 1;
    const int row0 = blockIdx.y * 128;
    const int col0 = blockIdx.x * 128;

    float d[4][4][4];
#pragma unroll
    for (int i = 0; i < 4; i++)
#pragma unroll
        for (int j = 0; j < 4; j++)
#pragma unroll
            for (int r = 0; r < 4; r++) d[i][j][r] = 0.f;

#pragma unroll
    for (int i = 0; i < 4; i++) {
        int cid  = t + 256 * i;
        int tile = cid >> 8;
        int idx  = cid & 255;
        int r    = idx >> 1;
        int c    = idx & 1;
        const __nv_bfloat16* gp;
        if (tile == 0)      gp = &Ahi[(size_t)(row0 + r) * DMODEL + c * 8];
        else if (tile == 1) gp = &Alo[(size_t)(row0 + r) * DMODEL + c * 8];
        else if (tile == 2) gp = &Bhi[(size_t)(col0 + r) * DMODEL + c * 8];
        else                gp = &Blo[(size_t)(col0 + r) * DMODEL + c * 8];
        uint32_t sa = smb + (uint32_t)(tile * TILE_E + r * GSTRIDE + c * 8) * 2u;
        CP_ASYNC16(sa, gp);
    }
    CP_COMMIT();

    int s = 0;
    for (int kc = 0; kc < 128; kc++) {
        if (kc + 1 < 128) {
            const int k0 = (kc + 1) * 16;
            const int sn = s ^ 1;
#pragma unroll
            for (int i = 0; i < 4; i++) {
                int cid  = t + 256 * i;
                int tile = cid >> 8;
                int idx  = cid & 255;
                int r    = idx >> 1;
                int c    = idx & 1;
                const __nv_bfloat16* gp;
                if (tile == 0)      gp = &Ahi[(size_t)(row0 + r) * DMODEL + k0 + c * 8];
                else if (tile == 1) gp = &Alo[(size_t)(row0 + r) * DMODEL + k0 + c * 8];
                else if (tile == 2) gp = &Bhi[(size_t)(col0 + r) * DMODEL + k0 + c * 8];
                else                gp = &Blo[(size_t)(col0 + r) * DMODEL + k0 + c * 8];
                uint32_t sa = smb + (uint32_t)(sn * STAGE_E + tile * TILE_E
                                               + r * GSTRIDE + c * 8) * 2u;
                CP_ASYNC16(sa, gp);
            }
            CP_COMMIT();
            CP_WAIT(1);
        } else {
            CP_WAIT(0);
        }
        __syncthreads();

        {
            const __nv_bfloat16* SAh = sm + s * STAGE_E;
            const __nv_bfloat16* SAl = SAh + TILE_E;
            const __nv_bfloat16* SBh = SAh + 2 * TILE_E;
            const __nv_bfloat16* SBl = SAh + 3 * TILE_E;
            uint32_t ah[4][4], al[4][4], bh[4][2], bl[4][2];
#pragma unroll
            for (int i = 0; i < 4; i++) {
                int off = (wm * 64 + i * 16 + g) * GSTRIDE + 2 * tg;
                ah[i][0] = *(const uint32_t*)(SAh + off);
                ah[i][1] = *(const uint32_t*)(SAh + off + 8 * GSTRIDE);
                ah[i][2] = *(const uint32_t*)(SAh + off + 8);
                ah[i][3] = *(const uint32_t*)(SAh + off + 8 * GSTRIDE + 8);
                al[i][0] = *(const uint32_t*)(SAl + off);
                al[i][1] = *(const uint32_t*)(SAl + off + 8 * GSTRIDE);
                al[i][2] = *(const uint32_t*)(SAl + off + 8);
                al[i][3] = *(const uint32_t*)(SAl + off + 8 * GSTRIDE + 8);
            }
#pragma unroll
            for (int j = 0; j < 4; j++) {
                int off = (wn * 32 + j * 8 + g) * GSTRIDE + 2 * tg;
                bh[j][0] = *(const uint32_t*)(SBh + off);
                bh[j][1] = *(const uint32_t*)(SBh + off + 8);
                bl[j][0] = *(const uint32_t*)(SBl + off);
                bl[j][1] = *(const uint32_t*)(SBl + off + 8);
            }
#pragma unroll
            for (int i = 0; i < 4; i++)
#pragma unroll
                for (int j = 0; j < 4; j++) {
                    MMA_BF16(d[i][j], ah[i], bh[j]);
                    MMA_BF16(d[i][j], ah[i], bl[j]);
                    MMA_BF16(d[i][j], al[i], bh[j]);
                }
        }
        __syncthreads();
        s ^= 1;
    }

#pragma unroll
    for (int j = 0; j < 4; j++) {
        const int col = col0 + wn * 32 + j * 8 + 2 * tg;
        const float b0 = bias[col], b1 = bias[col + 1];
#pragma unroll
        for (int i = 0; i < 4; i++) {
            const int ra = row0 + wm * 64 + i * 16 + g;
            float2 v0 = make_float2(d[i][j][0] + b0, d[i][j][1] + b1);
            float2 v1 = make_float2(d[i][j][2] + b0, d[i][j][3] + b1);
            *(float2*)&C[(size_t)ra * DMODEL + col]       = v0;
            *(float2*)&C[(size_t)(ra + 8) * DMODEL + col] = v1;
        }
    }
}

__global__ void __launch_bounds__(256, 1) qkv_bf16_gemm_kernel(
    const float* __restrict__ bq, const float* __restrict__ bk,
    const float* __restrict__ bv)
{
    if (blockIdx.z == 0)
        bf16s_gemm_body(g_Xhi, g_Xlo, g_Wqhi, g_Wqlo, bq, g_Q);
    else if (blockIdx.z == 1)
        bf16s_gemm_body(g_Xhi, g_Xlo, g_Wkhi, g_Wklo, bk, g_K);
    else
        bf16s_gemm_body(g_Xhi, g_Xlo, g_Wvhi, g_Wvlo, bv, g_V);
}

__global__ void __launch_bounds__(256, 1) o_bf16_gemm_kernel(
    const float* __restrict__ bo, float* __restrict__ out)
{
    bf16s_gemm_body(g_ctxhi, g_ctxlo, g_Wohi, g_Wolo, bo, out);
}

// ===========================================================================
// Head transpose: [l][d*32+h] -> [h][l][d].
//   y=0: Q -> g_Qf16 (scaled)   y=1: K -> g_Kf16   y=2: V -> g_Vh (fp32)
// ===========================================================================
__global__ void __launch_bounds__(256) head_transpose_kernel()
{
    const float* src; float scale = 1.f;
    if (blockIdx.y == 0)      { src = g_Q; scale = rsqrtf((float)DMODEL); }
    else if (blockIdx.y == 1) { src = g_K; }
    else                      { src = g_V; }

    __shared__ float s[4 * 2080];   // [l][h][d]: l*2080 + h*65 + d
    const int t  = threadIdx.x;
    const int l0 = blockIdx.x * 4;

#pragma unroll
    for (int i = 0; i < 8; i++) {
        int f4 = t + 256 * i;
        int l  = f4 >> 9;
        int n  = (f4 & 511) * 4;
        float4 v = *(const float4*)&src[(l0 + l) * DMODEL + n];
        s[l * 2080 + ((n + 0) & 31) * 65 + ((n + 0) >> 5)] = v.x * scale;
        s[l * 2080 + ((n + 1) & 31) * 65 + ((n + 1) >> 5)] = v.y * scale;
        s[l * 2080 + ((n + 2) & 31) * 65 + ((n + 2) >> 5)] = v.z * scale;
        s[l * 2080 + ((n + 3) & 31) * 65 + ((n + 3) >> 5)] = v.w * scale;
    }
    __syncthreads();

    if (blockIdx.y < 2) {
        __half* dst = (blockIdx.y == 0) ? g_Qf16 : g_Kf16;
#pragma unroll
        for (int i = 0; i < 8; i++) {
            int f4 = t + 256 * i;
            int dd = (f4 & 15) * 4;
            int l  = (f4 >> 4) & 3;
            int hh = f4 >> 6;
            int base = l * 2080 + hh * 65 + dd;
            __half2 u0 = __floats2half2_rn(s[base + 0], s[base + 1]);
            __half2 u1 = __floats2half2_rn(s[base + 2], s[base + 3]);
            uint2 u;
            u.x = *reinterpret_cast<uint32_t*>(&u0);
            u.y = *reinterpret_cast<uint32_t*>(&u1);
            *(uint2*)&dst[hh * (SEQ * DHEAD) + (l0 + l) * DHEAD + dd] = u;
        }
    } else {
#pragma unroll
        for (int i = 0; i < 8; i++) {
            int f4 = t + 256 * i;
            int dd = (f4 & 15) * 4;
            int l  = (f4 >> 4) & 3;
            int hh = f4 >> 6;
            int base = l * 2080 + hh * 65 + dd;
            float4 v;
            v.x = s[base + 0]; v.y = s[base + 1];
            v.z = s[base + 2]; v.w = s[base + 3];
            *(float4*)&g_Vh[hh * (SEQ * DHEAD) + (l0 + l) * DHEAD + dd] = v;
        }
    }
}

// ===========================================================================
// V transpose + fp16 hi/lo split: g_Vh [h][l][d] -> g_Vthi/lo [h][d][l]
// ===========================================================================
__global__ void __launch_bounds__(256) vtrans_kernel()
{
    const int h  = blockIdx.y;
    const int l0 = blockIdx.x * 64;
    const int t  = threadIdx.x;
    __shared__ float vs[64 * 65];
    const float* src = g_Vh + (size_t)h * SEQ * DHEAD;

#pragma unroll
    for (int i = 0; i < 16; i++) {
        int idx = t + 256 * i;           // 0..4095
        int l = idx >> 6, dd = idx & 63;
        vs[l * 65 + dd] = src[(size_t)(l0 + l) * DHEAD + dd];
    }
    __syncthreads();

#pragma unroll
    for (int i = 0; i < 8; i++) {
        int idx = t + 256 * i;           // 0..2047 half2 units
        int dd = idx >> 5, c2 = idx & 31;
        int l = c2 * 2;
        float f0 = vs[l * 65 + dd], f1 = vs[(l + 1) * 65 + dd];
        __half h0 = __float2half_rn(f0), h1 = __float2half_rn(f1);
        __half q0 = __float2half_rn(f0 - __half2float(h0));
        __half q1 = __float2half_rn(f1 - __half2float(h1));
        __half2 hi2 = __halves2half2(h0, h1);
        __half2 lo2 = __halves2half2(q0, q1);
        size_t off = (size_t)h * DHEAD * SEQ + (size_t)dd * SEQ + l0 + l;
        *(__half2*)&g_Vthi[off] = hi2;
        *(__half2*)&g_Vtlo[off] = lo2;
    }
}

// ===========================================================================
// Flash attention: fp16 HMMA for QK^T and PV, fp32 poly-exp2 softmax.
// CTA = (64 q-rows, head); 64 key-chunks of 32; 8 warps (4M x 2N).
// ===========================================================================
__global__ void __launch_bounds__(256) attn_kernel()
{
    const int h  = blockIdx.y;
    const int q0 = blockIdx.x * 64;
    const int t    = threadIdx.x;
    const int warp = t >> 5, lane = t & 31;
    const int g    = lane >> 2, tg = lane & 3;
    const int wm   = warp & 3,  wn = warp >> 2;   // 4 M-slots x 2 N-slots
    const int mb   = wm * 16;

    __shared__ __half Qs[64 * 72];
    __shared__ __half Ks[2][32 * 72];
    __shared__ __half Vhs[2][64 * 40];
    __shared__ __half Vls[2][64 * 40];
    __shared__ float  Sp[64 * 36];          // S fp32; P fp16 overlaid
    __shared__ float  alpha_s[64];
    __shared__ float  ls_s[64];

    const __half* Qg  = g_Qf16 + (size_t)h * SEQ * DHEAD;
    const __half* Kg  = g_Kf16 + (size_t)h * SEQ * DHEAD;
    const __half* Vhg = g_Vthi + (size_t)h * DHEAD * SEQ;
    const __half* Vlg = g_Vtlo + (size_t)h * DHEAD * SEQ;
    __half* Ph = (__half*)Sp;

    // stage Q (64x64 halves)
#pragma unroll
    for (int i = 0; i < 2; i++) {
        int idx = t + 256 * i;
        int r = idx >> 3, c8 = (idx & 7) * 8;
        *(uint4*)&Qs[r * 72 + c8] = *(const uint4*)&Qg[(size_t)(q0 + r) * DHEAD + c8];
    }

    // preload K/V chunk 0
    {
        int rK = t >> 3, cK = (t & 7) * 8;
        CP_ASYNC16(smem_to_u32(&Ks[0][rK * 72 + cK]), &Kg[(size_t)rK * DHEAD + cK]);
        int rV = t >> 2, cV = (t & 3) * 8;
        CP_ASYNC16(smem_to_u32(&Vhs[0][rV * 40 + cV]), &Vhg[(size_t)rV * SEQ + cV]);
        CP_ASYNC16(smem_to_u32(&Vls[0][rV * 40 + cV]), &Vlg[(size_t)rV * SEQ + cV]);
        CP_COMMIT();
    }

    float m_r = -1e30f, l_r = 0.f;
    const int sr = t >> 2, sc = (t & 3) * 8;
    float o[4][4];
#pragma unroll
    for (int j = 0; j < 4; j++)
#pragma unroll
        for (int r = 0; r < 4; r++) o[j][r] = 0.f;

    __syncthreads();   // Q staged
    uint32_t aq[4][4];
#pragma unroll
    for (int k4 = 0; k4 < 4; k4++) {
        int off = (mb + g) * 72 + k4 * 16 + 2 * tg;
        aq[k4][0] = *(const uint32_t*)&Qs[off];
        aq[k4][1] = *(const uint32_t*)&Qs[off + 8 * 72];
        aq[k4][2] = *(const uint32_t*)&Qs[off + 8];
        aq[k4][3] = *(const uint32_t*)&Qs[off + 8 * 72 + 8];
    }

    int b = 0;
    for (int kt = 0; kt < SEQ / 32; kt++) {
        if (kt + 1 < SEQ / 32) {
            const int k0n = (kt + 1) * 32, bn = b ^ 1;
            int rK = t >> 3, cK = (t & 7) * 8;
            CP_ASYNC16(smem_to_u32(&Ks[bn][rK * 72 + cK]),
                       &Kg[(size_t)(k0n + rK) * DHEAD + cK]);
            int rV = t >> 2, cV = (t & 3) * 8;
            CP_ASYNC16(smem_to_u32(&Vhs[bn][rV * 40 + cV]),
                       &Vhg[(size_t)rV * SEQ + k0n + cV]);
            CP_ASYNC16(smem_to_u32(&Vls[bn][rV * 40 + cV]),
                       &Vlg[(size_t)rV * SEQ + k0n + cV]);
            CP_COMMIT();
            CP_WAIT(1);
        } else {
            CP_WAIT(0);
        }
        __syncthreads();

        // ---- S = Q K^T (fp16 MMA, fp32 accum) ----
        float c0f[4] = {0.f, 0.f, 0.f, 0.f};
        float c1f[4] = {0.f, 0.f, 0.f, 0.f};
#pragma unroll
        for (int k4 = 0; k4 < 4; k4++) {
            uint32_t kb0[2], kb1[2];
            int off0 = (wn * 16 + g) * 72 + k4 * 16 + 2 * tg;
            kb0[0] = *(const uint32_t*)&Ks[b][off0];
            kb0[1] = *(const uint32_t*)&Ks[b][off0 + 8];
            int off1 = (wn * 16 + 8 + g) * 72 + k4 * 16 + 2 * tg;
            kb1[0] = *(const uint32_t*)&Ks[b][off1];
            kb1[1] = *(const uint32_t*)&Ks[b][off1 + 8];
            MMA_F16(c0f, aq[k4], kb0);
            MMA_F16(c1f, aq[k4], kb1);
        }
        {
            int col0 = wn * 16 + 2 * tg;
            *(float2*)&Sp[(mb + g) * 36 + col0]         = make_float2(c0f[0], c0f[1]);
            *(float2*)&Sp[(mb + g + 8) * 36 + col0]     = make_float2(c0f[2], c0f[3]);
            *(float2*)&Sp[(mb + g) * 36 + col0 + 8]     = make_float2(c1f[0], c1f[1]);
            *(float2*)&Sp[(mb + g + 8) * 36 + col0 + 8] = make_float2(c1f[2], c1f[3]);
        }
        __syncthreads();   // S visible

        // ---- online softmax (4 threads/row, 8 keys each; fp32 poly exp2) ----
        float4 s0 = *(const float4*)&Sp[sr * 36 + sc];
        float4 s1 = *(const float4*)&Sp[sr * 36 + sc + 4];
        __syncthreads();   // all S reads done; P may overwrite
        {
            float lm = fmaxf(fmaxf(fmaxf(s0.x, s0.y), fmaxf(s0.z, s0.w)),
                             fmaxf(fmaxf(s1.x, s1.y), fmaxf(s1.z, s1.w)));
            lm = fmaxf(lm, __shfl_xor_sync(0xffffffffu, lm, 1));
            lm = fmaxf(lm, __shfl_xor_sync(0xffffffffu, lm, 2));
            float mnew  = fmaxf(m_r, lm);
            float alpha = exp2_poly((m_r - mnew) * LOG2E);
            float mny   = mnew * LOG2E;
            float p0 = exp2_poly(fmaf(s0.x, LOG2E, -mny));
            float p1 = exp2_poly(fmaf(s0.y, LOG2E, -mny));
            float p2 = exp2_poly(fmaf(s0.z, LOG2E, -mny));
            float p3 = exp2_poly(fmaf(s0.w, LOG2E, -mny));
            float p4 = exp2_poly(fmaf(s1.x, LOG2E, -mny));
            float p5 = exp2_poly(fmaf(s1.y, LOG2E, -mny));
            float p6 = exp2_poly(fmaf(s1.z, LOG2E, -mny));
            float p7 = exp2_poly(fmaf(s1.w, LOG2E, -mny));
            __half2 h01 = __floats2half2_rn(p0, p1);
            __half2 h23 = __floats2half2_rn(p2, p3);
            __half2 h45 = __floats2half2_rn(p4, p5);
            __half2 h67 = __floats2half2_rn(p6, p7);
            uint2 u0, u1;
            u0.x = *reinterpret_cast<uint32_t*>(&h01);
            u0.y = *reinterpret_cast<uint32_t*>(&h23);
            u1.x = *reinterpret_cast<uint32_t*>(&h45);
            u1.y = *reinterpret_cast<uint32_t*>(&h67);
            *(uint2*)&Ph[sr * 72 + sc]     = u0;
            *(uint2*)&Ph[sr * 72 + sc + 4] = u1;
            float psum = ((p0 + p1) + (p2 + p3)) + ((p4 + p5) + (p6 + p7));
            psum += __shfl_xor_sync(0xffffffffu, psum, 1);
            psum += __shfl_xor_sync(0xffffffffu, psum, 2);
            l_r = l_r * alpha + psum;
            m_r = mnew;
            if ((t & 3) == 0) {
                alpha_s[sr] = alpha;
                if (kt == SEQ / 32 - 1) ls_s[sr] = 1.f / l_r;
            }
        }
        __syncthreads();   // P + alpha visible

        // ---- O rescale + PV (2 fp16 combos: P*Vh + P*Vl) ----
        {
            float a0 = alpha_s[mb + g], a1 = alpha_s[mb + g + 8];
#pragma unroll
            for (int j = 0; j < 4; j++) {
                o[j][0] *= a0; o[j][1] *= a0;
                o[j][2] *= a1; o[j][3] *= a1;
            }
#pragma unroll
            for (int ks = 0; ks < 2; ks++) {
                int ko = ks * 16;
                uint32_t pa[4];
                pa[0] = *(const uint32_t*)&Ph[(mb + g) * 72 + ko + 2 * tg];
                pa[1] = *(const uint32_t*)&Ph[(mb + g + 8) * 72 + ko + 2 * tg];
                pa[2] = *(const uint32_t*)&Ph[(mb + g) * 72 + ko + 8 + 2 * tg];
                pa[3] = *(const uint32_t*)&Ph[(mb + g + 8) * 72 + ko + 8 + 2 * tg];
#pragma unroll
                for (int j = 0; j < 4; j++) {
                    int n = wn * 32 + j * 8 + g;
                    uint32_t vb[2], vl[2];
                    vb[0] = *(const uint32_t*)&Vhs[b][n * 40 + ko + 2 * tg];
                    vb[1] = *(const uint32_t*)&Vhs[b][n * 40 + ko + 8 + 2 * tg];
                    vl[0] = *(const uint32_t*)&Vls[b][n * 40 + ko + 2 * tg];
                    vl[1] = *(const uint32_t*)&Vls[b][n * 40 + ko + 8 + 2 * tg];
                    MMA_F16(o[j], pa, vb);
                    MMA_F16(o[j], pa, vl);
                }
            }
        }
        // CRITICAL: all warps must finish reading Vhs[b]/Vls[b]/Ph before the
        // next iteration's cp.async prefetch overwrites buffer b (the race
        // that caused R8/R9's 3.5e-3 error). Mirrors the trailing barrier in
        // the validated GEMM mainloop.
        __syncthreads();
        b ^= 1;
    }

    // epilogue: ctx[(q0+r)][d*32+h]
    float inv0 = ls_s[mb + g], inv1 = ls_s[mb + g + 8];
#pragma unroll
    for (int j = 0; j < 4; j++) {
        int d0 = wn * 32 + j * 8 + 2 * tg;
        int r0 = q0 + mb + g, r1 = r0 + 8;
        g_ctx[(size_t)r0 * DMODEL + d0 * NHEADS + h]       = o[j][0] * inv0;
        g_ctx[(size_t)r0 * DMODEL + (d0 + 1) * NHEADS + h] = o[j][1] * inv0;
        g_ctx[(size_t)r1 * DMODEL + d0 * NHEADS + h]       = o[j][2] * inv1;
        g_ctx[(size_t)r1 * DMODEL + (d0 + 1) * NHEADS + h] = o[j][3] * inv1;
    }
}

// ===========================================================================
extern "C" void kernel_launch(void* const* d_in, const int* in_sizes, int n_in,
                              void* d_out, int out_size)
{
    (void)in_sizes; (void)n_in; (void)out_size;
    const float* X  = (const float*)d_in[0];
    const float* Wq = (const float*)d_in[1];
    const float* bq = (const float*)d_in[2];
    const float* Wk = (const float*)d_in[3];
    const float* bk = (const float*)d_in[4];
    const float* Wv = (const float*)d_in[5];
    const float* bv = (const float*)d_in[6];
    const float* Wo = (const float*)d_in[7];
    const float* bo = (const float*)d_in[8];
    float* out = (float*)d_out;

    const int SPLIT_GRID = (SEQ * DMODEL / 4) / 256;  // 4096
    split_kernel<<<SPLIT_GRID, 256>>>(X,  0);
    split_kernel<<<SPLIT_GRID, 256>>>(Wq, 1);
    split_kernel<<<SPLIT_GRID, 256>>>(Wk, 2);
    split_kernel<<<SPLIT_GRID, 256>>>(Wv, 3);
    split_kernel<<<SPLIT_GRID, 256>>>(Wo, 4);

    qkv_bf16_gemm_kernel<<<dim3(16, 16, 3), 256, GEMM_SMEM>>>(bq, bk, bv);
    head_transpose_kernel<<<dim3(SEQ / 4, 3), 256>>>();
    vtrans_kernel<<<dim3(SEQ / 64, NHEADS), 256>>>();
    attn_kernel<<<dim3(SEQ / 64, NHEADS), 256>>>();
    split_kernel<<<SPLIT_GRID, 256>>>(nullptr, 5);
    o_bf16_gemm_kernel<<<dim3(16, 16), 256, GEMM_SMEM>>>(bo, out);
}

// round 14
// speedup vs baseline: 3.1221x; 1.4412x over previous
#include <cuda_runtime.h>
#include <cuda_bf16.h>
#include <cuda_fp16.h>
#include <cstdint>

#define SEQ    2048
#define DMODEL 2048
#define NHEADS 32
#define DHEAD  64
#define LOG2E  1.4426950408889634f

// ===========================================================================
// Scratch (allocation-free rule: __device__ globals)
// ===========================================================================
__device__ float g_Q[SEQ * DMODEL];
__device__ float g_K[SEQ * DMODEL];
__device__ float g_V[SEQ * DMODEL];
__device__ float g_Vh[SEQ * DMODEL];      // [h][l][d] fp32 (staging for vtrans)
__device__ float g_ctx[SEQ * DMODEL];

__device__ __half g_Qf16[SEQ * DMODEL];   // [h][l][d], pre-scaled by 1/sqrt(dm)
__device__ __half g_Kf16[SEQ * DMODEL];   // [h][l][d]
__device__ __half g_Vthi[SEQ * DMODEL];   // [h][d][l] hi
__device__ __half g_Vtlo[SEQ * DMODEL];   // [h][d][l] lo

// fp16 hi/lo splits for the GEMMs (lo of weights is computed but unused)
__device__ __half g_Xhi[SEQ * DMODEL],     g_Xlo[SEQ * DMODEL];
__device__ __half g_Wqhi[DMODEL * DMODEL], g_Wqlo[DMODEL * DMODEL];
__device__ __half g_Wkhi[DMODEL * DMODEL], g_Wklo[DMODEL * DMODEL];
__device__ __half g_Wvhi[DMODEL * DMODEL], g_Wvlo[DMODEL * DMODEL];
__device__ __half g_Wohi[DMODEL * DMODEL], g_Wolo[DMODEL * DMODEL];
__device__ __half g_ctxhi[SEQ * DMODEL],   g_ctxlo[SEQ * DMODEL];

__device__ __forceinline__ uint32_t smem_to_u32(const void* p) {
    uint32_t a;
    asm("{ .reg .u64 t; cvta.to.shared.u64 t, %1; cvt.u32.u64 %0, t; }"
        : "=r"(a) : "l"(p));
    return a;
}

// fp32 exp2 on the FMA pipe: 2^x = 2^n * poly(f), n=rint(x), f in [-0.5,0.5].
// Degree-5 Taylor, rel err <= 3.4e-6. Valid for x <= 0 (clamped at -200).
__device__ __forceinline__ float exp2_poly(float x) {
    x = fmaxf(x, -200.f);
    float n = rintf(x);
    float f = x - n;
    float p = 1.3333558e-3f;
    p = fmaf(p, f, 9.6181291e-3f);
    p = fmaf(p, f, 5.5504109e-2f);
    p = fmaf(p, f, 2.4022651e-1f);
    p = fmaf(p, f, 6.9314718e-1f);
    p = fmaf(p, f, 1.0f);
    int e = (int)n;
    e = (e < -126) ? -126 : e;
    return p * __int_as_float((uint32_t)(e + 127) << 23);
}

#define MMA_F16(d, a, b) \
    asm volatile("mma.sync.aligned.m16n8k16.row.col.f32.f16.f16.f32 " \
        "{%0,%1,%2,%3}, {%4,%5,%6,%7}, {%8,%9}, {%0,%1,%2,%3};" \
        : "+f"((d)[0]), "+f"((d)[1]), "+f"((d)[2]), "+f"((d)[3]) \
        : "r"((a)[0]), "r"((a)[1]), "r"((a)[2]), "r"((a)[3]), \
          "r"((b)[0]), "r"((b)[1]))

#define CP_ASYNC16(sa, gp) \
    asm volatile("cp.async.cg.shared.global [%0], [%1], 16;" \
                 :: "r"(sa), "l"(gp) : "memory")
#define CP_COMMIT()  asm volatile("cp.async.commit_group;" ::: "memory")
#define CP_WAIT(n)   asm volatile("cp.async.wait_group %0;" :: "n"(n) : "memory")

// ===========================================================================
// fp32 -> (hi, lo) fp16 split.  which: 0=X 1=Wq 2=Wk 3=Wv 4=Wo 5=ctx
// ===========================================================================
__global__ void __launch_bounds__(256) split_kernel(const float* __restrict__ src, int which)
{
    __half* hi; __half* lo;
    switch (which) {
        case 0: hi = g_Xhi;  lo = g_Xlo;  break;
        case 1: hi = g_Wqhi; lo = g_Wqlo; break;
        case 2: hi = g_Wkhi; lo = g_Wklo; break;
        case 3: hi = g_Wvhi; lo = g_Wvlo; break;
        case 4: hi = g_Wohi; lo = g_Wolo; break;
        default: hi = g_ctxhi; lo = g_ctxlo; src = g_ctx; break;
    }
    int i = (blockIdx.x * 256 + threadIdx.x) * 4;
    float4 v = *(const float4*)&src[i];
    __half h0 = __float2half_rn(v.x);
    __half h1 = __float2half_rn(v.y);
    __half h2 = __float2half_rn(v.z);
    __half h3 = __float2half_rn(v.w);
    __half l0 = __float2half_rn(v.x - __half2float(h0));
    __half l1 = __float2half_rn(v.y - __half2float(h1));
    __half l2 = __float2half_rn(v.z - __half2float(h2));
    __half l3 = __float2half_rn(v.w - __half2float(h3));
    ushort4 hv, lv;
    hv.x = __half_as_ushort(h0); hv.y = __half_as_ushort(h1);
    hv.z = __half_as_ushort(h2); hv.w = __half_as_ushort(h3);
    lv.x = __half_as_ushort(l0); lv.y = __half_as_ushort(l1);
    lv.z = __half_as_ushort(l2); lv.w = __half_as_ushort(l3);
    *(ushort4*)&hi[i] = hv;
    *(ushort4*)&lo[i] = lv;
}

// ===========================================================================
// fp16-split NT GEMM via mma.sync: C = A @ B^T + bias, 2048^3.
// 128x128 CTA tile, 8 warps (warp tile 64x32), BK=16, cp.async double-buffer.
// 2 combos per K-16 step: Ah*Bh + Al*Bh  (Ah*Bl dropped: ~1e-4 RMS rel err).
// smem: [stage][tile(Ah,Al,Bh)][128][24] fp16 = 36864 B total (<48K default)
// ===========================================================================
#define GSTRIDE   24
#define TILE_E    (128 * GSTRIDE)      // 3072 elems per tile
#define STAGE_E   (3 * TILE_E)         // 9216 elems per stage
#define GEMM_SMEM (2 * STAGE_E * 2)    // 36864 bytes

__device__ __forceinline__ void f16s_gemm_body(
    const __half* __restrict__ Ahi, const __half* __restrict__ Alo,
    const __half* __restrict__ Bhi,
    const float* __restrict__ bias, float* __restrict__ C)
{
    extern __shared__ __half sm[];
    const uint32_t smb = smem_to_u32(sm);

    const int t    = threadIdx.x;
    const int warp = t >> 5;
    const int lane = t & 31;
    const int g    = lane >> 2;
    const int tg   = lane & 3;
    const int wm   = warp & 1;
    const int wn   = warp >> 1;
    const int row0 = blockIdx.y * 128;
    const int col0 = blockIdx.x * 128;

    float d[4][4][4];
#pragma unroll
    for (int i = 0; i < 4; i++)
#pragma unroll
        for (int j = 0; j < 4; j++)
#pragma unroll
            for (int r = 0; r < 4; r++) d[i][j][r] = 0.f;

    // prefetch stage 0 (3 tiles x 256 16B-chunks = 768; 3 per thread)
#pragma unroll
    for (int i = 0; i < 3; i++) {
        int cid  = t + 256 * i;
        int tile = cid >> 8;
        int idx  = cid & 255;
        int r    = idx >> 1;
        int c    = idx & 1;
        const __half* gp;
        if (tile == 0)      gp = &Ahi[(size_t)(row0 + r) * DMODEL + c * 8];
        else if (tile == 1) gp = &Alo[(size_t)(row0 + r) * DMODEL + c * 8];
        else                gp = &Bhi[(size_t)(col0 + r) * DMODEL + c * 8];
        uint32_t sa = smb + (uint32_t)(tile * TILE_E + r * GSTRIDE + c * 8) * 2u;
        CP_ASYNC16(sa, gp);
    }
    CP_COMMIT();

    int s = 0;
    for (int kc = 0; kc < 128; kc++) {
        if (kc + 1 < 128) {
            const int k0 = (kc + 1) * 16;
            const int sn = s ^ 1;
#pragma unroll
            for (int i = 0; i < 3; i++) {
                int cid  = t + 256 * i;
                int tile = cid >> 8;
                int idx  = cid & 255;
                int r    = idx >> 1;
                int c    = idx & 1;
                const __half* gp;
                if (tile == 0)      gp = &Ahi[(size_t)(row0 + r) * DMODEL + k0 + c * 8];
                else if (tile == 1) gp = &Alo[(size_t)(row0 + r) * DMODEL + k0 + c * 8];
                else                gp = &Bhi[(size_t)(col0 + r) * DMODEL + k0 + c * 8];
                uint32_t sa = smb + (uint32_t)(sn * STAGE_E + tile * TILE_E
                                               + r * GSTRIDE + c * 8) * 2u;
                CP_ASYNC16(sa, gp);
            }
            CP_COMMIT();
            CP_WAIT(1);
        } else {
            CP_WAIT(0);
        }
        __syncthreads();

        {
            const __half* SAh = sm + s * STAGE_E;
            const __half* SAl = SAh + TILE_E;
            const __half* SBh = SAh + 2 * TILE_E;
            uint32_t ah[4][4], al[4][4], bh[4][2];
#pragma unroll
            for (int i = 0; i < 4; i++) {
                int off = (wm * 64 + i * 16 + g) * GSTRIDE + 2 * tg;
                ah[i][0] = *(const uint32_t*)(SAh + off);
                ah[i][1] = *(const uint32_t*)(SAh + off + 8 * GSTRIDE);
                ah[i][2] = *(const uint32_t*)(SAh + off + 8);
                ah[i][3] = *(const uint32_t*)(SAh + off + 8 * GSTRIDE + 8);
                al[i][0] = *(const uint32_t*)(SAl + off);
                al[i][1] = *(const uint32_t*)(SAl + off + 8 * GSTRIDE);
                al[i][2] = *(const uint32_t*)(SAl + off + 8);
                al[i][3] = *(const uint32_t*)(SAl + off + 8 * GSTRIDE + 8);
            }
#pragma unroll
            for (int j = 0; j < 4; j++) {
                int off = (wn * 32 + j * 8 + g) * GSTRIDE + 2 * tg;
                bh[j][0] = *(const uint32_t*)(SBh + off);
                bh[j][1] = *(const uint32_t*)(SBh + off + 8);
            }
#pragma unroll
            for (int i = 0; i < 4; i++)
#pragma unroll
                for (int j = 0; j < 4; j++) {
                    MMA_F16(d[i][j], ah[i], bh[j]);
                    MMA_F16(d[i][j], al[i], bh[j]);
                }
        }
        __syncthreads();
        s ^= 1;
    }

#pragma unroll
    for (int j = 0; j < 4; j++) {
        const int col = col0 + wn * 32 + j * 8 + 2 * tg;
        const float b0 = bias[col], b1 = bias[col + 1];
#pragma unroll
        for (int i = 0; i < 4; i++) {
            const int ra = row0 + wm * 64 + i * 16 + g;
            float2 v0 = make_float2(d[i][j][0] + b0, d[i][j][1] + b1);
            float2 v1 = make_float2(d[i][j][2] + b0, d[i][j][3] + b1);
            *(float2*)&C[(size_t)ra * DMODEL + col]       = v0;
            *(float2*)&C[(size_t)(ra + 8) * DMODEL + col] = v1;
        }
    }
}

__global__ void __launch_bounds__(256, 1) qkv_f16_gemm_kernel(
    const float* __restrict__ bq, const float* __restrict__ bk,
    const float* __restrict__ bv)
{
    if (blockIdx.z == 0)
        f16s_gemm_body(g_Xhi, g_Xlo, g_Wqhi, bq, g_Q);
    else if (blockIdx.z == 1)
        f16s_gemm_body(g_Xhi, g_Xlo, g_Wkhi, bk, g_K);
    else
        f16s_gemm_body(g_Xhi, g_Xlo, g_Wvhi, bv, g_V);
}

__global__ void __launch_bounds__(256, 1) o_f16_gemm_kernel(
    const float* __restrict__ bo, float* __restrict__ out)
{
    f16s_gemm_body(g_ctxhi, g_ctxlo, g_Wohi, bo, out);
}

// ===========================================================================
// Head transpose: [l][d*32+h] -> [h][l][d].
//   y=0: Q -> g_Qf16 (scaled)   y=1: K -> g_Kf16   y=2: V -> g_Vh (fp32)
// ===========================================================================
__global__ void __launch_bounds__(256) head_transpose_kernel()
{
    const float* src; float scale = 1.f;
    if (blockIdx.y == 0)      { src = g_Q; scale = rsqrtf((float)DMODEL); }
    else if (blockIdx.y == 1) { src = g_K; }
    else                      { src = g_V; }

    __shared__ float s[4 * 2080];   // [l][h][d]: l*2080 + h*65 + d
    const int t  = threadIdx.x;
    const int l0 = blockIdx.x * 4;

#pragma unroll
    for (int i = 0; i < 8; i++) {
        int f4 = t + 256 * i;
        int l  = f4 >> 9;
        int n  = (f4 & 511) * 4;
        float4 v = *(const float4*)&src[(l0 + l) * DMODEL + n];
        s[l * 2080 + ((n + 0) & 31) * 65 + ((n + 0) >> 5)] = v.x * scale;
        s[l * 2080 + ((n + 1) & 31) * 65 + ((n + 1) >> 5)] = v.y * scale;
        s[l * 2080 + ((n + 2) & 31) * 65 + ((n + 2) >> 5)] = v.z * scale;
        s[l * 2080 + ((n + 3) & 31) * 65 + ((n + 3) >> 5)] = v.w * scale;
    }
    __syncthreads();

    if (blockIdx.y < 2) {
        __half* dst = (blockIdx.y == 0) ? g_Qf16 : g_Kf16;
#pragma unroll
        for (int i = 0; i < 8; i++) {
            int f4 = t + 256 * i;
            int dd = (f4 & 15) * 4;
            int l  = (f4 >> 4) & 3;
            int hh = f4 >> 6;
            int base = l * 2080 + hh * 65 + dd;
            __half2 u0 = __floats2half2_rn(s[base + 0], s[base + 1]);
            __half2 u1 = __floats2half2_rn(s[base + 2], s[base + 3]);
            uint2 u;
            u.x = *reinterpret_cast<uint32_t*>(&u0);
            u.y = *reinterpret_cast<uint32_t*>(&u1);
            *(uint2*)&dst[hh * (SEQ * DHEAD) + (l0 + l) * DHEAD + dd] = u;
        }
    } else {
#pragma unroll
        for (int i = 0; i < 8; i++) {
            int f4 = t + 256 * i;
            int dd = (f4 & 15) * 4;
            int l  = (f4 >> 4) & 3;
            int hh = f4 >> 6;
            int base = l * 2080 + hh * 65 + dd;
            float4 v;
            v.x = s[base + 0]; v.y = s[base + 1];
            v.z = s[base + 2]; v.w = s[base + 3];
            *(float4*)&g_Vh[hh * (SEQ * DHEAD) + (l0 + l) * DHEAD + dd] = v;
        }
    }
}

// ===========================================================================
// V transpose + fp16 hi/lo split: g_Vh [h][l][d] -> g_Vthi/lo [h][d][l]
// ===========================================================================
__global__ void __launch_bounds__(256) vtrans_kernel()
{
    const int h  = blockIdx.y;
    const int l0 = blockIdx.x * 64;
    const int t  = threadIdx.x;
    __shared__ float vs[64 * 65];
    const float* src = g_Vh + (size_t)h * SEQ * DHEAD;

#pragma unroll
    for (int i = 0; i < 16; i++) {
        int idx = t + 256 * i;           // 0..4095
        int l = idx >> 6, dd = idx & 63;
        vs[l * 65 + dd] = src[(size_t)(l0 + l) * DHEAD + dd];
    }
    __syncthreads();

#pragma unroll
    for (int i = 0; i < 8; i++) {
        int idx = t + 256 * i;           // 0..2047 half2 units
        int dd = idx >> 5, c2 = idx & 31;
        int l = c2 * 2;
        float f0 = vs[l * 65 + dd], f1 = vs[(l + 1) * 65 + dd];
        __half h0 = __float2half_rn(f0), h1 = __float2half_rn(f1);
        __half q0 = __float2half_rn(f0 - __half2float(h0));
        __half q1 = __float2half_rn(f1 - __half2float(h1));
        __half2 hi2 = __halves2half2(h0, h1);
        __half2 lo2 = __halves2half2(q0, q1);
        size_t off = (size_t)h * DHEAD * SEQ + (size_t)dd * SEQ + l0 + l;
        *(__half2*)&g_Vthi[off] = hi2;
        *(__half2*)&g_Vtlo[off] = lo2;
    }
}

// ===========================================================================
// Flash attention: fp16 HMMA for QK^T and PV, fp32 poly-exp2 softmax.
// CTA = (64 q-rows, head); 64 key-chunks of 32; 8 warps (4M x 2N).
// ===========================================================================
__global__ void __launch_bounds__(256) attn_kernel()
{
    const int h  = blockIdx.y;
    const int q0 = blockIdx.x * 64;
    const int t    = threadIdx.x;
    const int warp = t >> 5, lane = t & 31;
    const int g    = lane >> 2, tg = lane & 3;
    const int wm   = warp & 3,  wn = warp >> 2;   // 4 M-slots x 2 N-slots
    const int mb   = wm * 16;

    __shared__ __half Qs[64 * 72];
    __shared__ __half Ks[2][32 * 72];
    __shared__ __half Vhs[2][64 * 40];
    __shared__ __half Vls[2][64 * 40];
    __shared__ float  Sp[64 * 36];          // S fp32; P fp16 overlaid
    __shared__ float  alpha_s[64];
    __shared__ float  ls_s[64];

    const __half* Qg  = g_Qf16 + (size_t)h * SEQ * DHEAD;
    const __half* Kg  = g_Kf16 + (size_t)h * SEQ * DHEAD;
    const __half* Vhg = g_Vthi + (size_t)h * DHEAD * SEQ;
    const __half* Vlg = g_Vtlo + (size_t)h * DHEAD * SEQ;
    __half* Ph = (__half*)Sp;

    // stage Q (64x64 halves)
#pragma unroll
    for (int i = 0; i < 2; i++) {
        int idx = t + 256 * i;
        int r = idx >> 3, c8 = (idx & 7) * 8;
        *(uint4*)&Qs[r * 72 + c8] = *(const uint4*)&Qg[(size_t)(q0 + r) * DHEAD + c8];
    }

    // preload K/V chunk 0
    {
        int rK = t >> 3, cK = (t & 7) * 8;
        CP_ASYNC16(smem_to_u32(&Ks[0][rK * 72 + cK]), &Kg[(size_t)rK * DHEAD + cK]);
        int rV = t >> 2, cV = (t & 3) * 8;
        CP_ASYNC16(smem_to_u32(&Vhs[0][rV * 40 + cV]), &Vhg[(size_t)rV * SEQ + cV]);
        CP_ASYNC16(smem_to_u32(&Vls[0][rV * 40 + cV]), &Vlg[(size_t)rV * SEQ + cV]);
        CP_COMMIT();
    }

    float m_r = -1e30f, l_r = 0.f;
    const int sr = t >> 2, sc = (t & 3) * 8;
    float o[4][4];
#pragma unroll
    for (int j = 0; j < 4; j++)
#pragma unroll
        for (int r = 0; r < 4; r++) o[j][r] = 0.f;

    __syncthreads();   // Q staged
    uint32_t aq[4][4];
#pragma unroll
    for (int k4 = 0; k4 < 4; k4++) {
        int off = (mb + g) * 72 + k4 * 16 + 2 * tg;
        aq[k4][0] = *(const uint32_t*)&Qs[off];
        aq[k4][1] = *(const uint32_t*)&Qs[off + 8 * 72];
        aq[k4][2] = *(const uint32_t*)&Qs[off + 8];
        aq[k4][3] = *(const uint32_t*)&Qs[off + 8 * 72 + 8];
    }

    int b = 0;
    for (int kt = 0; kt < SEQ / 32; kt++) {
        if (kt + 1 < SEQ / 32) {
            const int k0n = (kt + 1) * 32, bn = b ^ 1;
            int rK = t >> 3, cK = (t & 7) * 8;
            CP_ASYNC16(smem_to_u32(&Ks[bn][rK * 72 + cK]),
                       &Kg[(size_t)(k0n + rK) * DHEAD + cK]);
            int rV = t >> 2, cV = (t & 3) * 8;
            CP_ASYNC16(smem_to_u32(&Vhs[bn][rV * 40 + cV]),
                       &Vhg[(size_t)rV * SEQ + k0n + cV]);
            CP_ASYNC16(smem_to_u32(&Vls[bn][rV * 40 + cV]),
                       &Vlg[(size_t)rV * SEQ + k0n + cV]);
            CP_COMMIT();
            CP_WAIT(1);
        } else {
            CP_WAIT(0);
        }
        __syncthreads();

        // ---- S = Q K^T (fp16 MMA, fp32 accum) ----
        float c0f[4] = {0.f, 0.f, 0.f, 0.f};
        float c1f[4] = {0.f, 0.f, 0.f, 0.f};
#pragma unroll
        for (int k4 = 0; k4 < 4; k4++) {
            uint32_t kb0[2], kb1[2];
            int off0 = (wn * 16 + g) * 72 + k4 * 16 + 2 * tg;
            kb0[0] = *(const uint32_t*)&Ks[b][off0];
            kb0[1] = *(const uint32_t*)&Ks[b][off0 + 8];
            int off1 = (wn * 16 + 8 + g) * 72 + k4 * 16 + 2 * tg;
            kb1[0] = *(const uint32_t*)&Ks[b][off1];
            kb1[1] = *(const uint32_t*)&Ks[b][off1 + 8];
            MMA_F16(c0f, aq[k4], kb0);
            MMA_F16(c1f, aq[k4], kb1);
        }
        {
            int col0 = wn * 16 + 2 * tg;
            *(float2*)&Sp[(mb + g) * 36 + col0]         = make_float2(c0f[0], c0f[1]);
            *(float2*)&Sp[(mb + g + 8) * 36 + col0]     = make_float2(c0f[2], c0f[3]);
            *(float2*)&Sp[(mb + g) * 36 + col0 + 8]     = make_float2(c1f[0], c1f[1]);
            *(float2*)&Sp[(mb + g + 8) * 36 + col0 + 8] = make_float2(c1f[2], c1f[3]);
        }
        __syncthreads();   // S visible

        // ---- online softmax (4 threads/row, 8 keys each; fp32 poly exp2) ----
        float4 s0 = *(const float4*)&Sp[sr * 36 + sc];
        float4 s1 = *(const float4*)&Sp[sr * 36 + sc + 4];
        __syncthreads();   // all S reads done; P may overwrite
        {
            float lm = fmaxf(fmaxf(fmaxf(s0.x, s0.y), fmaxf(s0.z, s0.w)),
                             fmaxf(fmaxf(s1.x, s1.y), fmaxf(s1.z, s1.w)));
            lm = fmaxf(lm, __shfl_xor_sync(0xffffffffu, lm, 1));
            lm = fmaxf(lm, __shfl_xor_sync(0xffffffffu, lm, 2));
            float mnew  = fmaxf(m_r, lm);
            float alpha = exp2_poly((m_r - mnew) * LOG2E);
            float mny   = mnew * LOG2E;
            float p0 = exp2_poly(fmaf(s0.x, LOG2E, -mny));
            float p1 = exp2_poly(fmaf(s0.y, LOG2E, -mny));
            float p2 = exp2_poly(fmaf(s0.z, LOG2E, -mny));
            float p3 = exp2_poly(fmaf(s0.w, LOG2E, -mny));
            float p4 = exp2_poly(fmaf(s1.x, LOG2E, -mny));
            float p5 = exp2_poly(fmaf(s1.y, LOG2E, -mny));
            float p6 = exp2_poly(fmaf(s1.z, LOG2E, -mny));
            float p7 = exp2_poly(fmaf(s1.w, LOG2E, -mny));
            __half2 h01 = __floats2half2_rn(p0, p1);
            __half2 h23 = __floats2half2_rn(p2, p3);
            __half2 h45 = __floats2half2_rn(p4, p5);
            __half2 h67 = __floats2half2_rn(p6, p7);
            uint2 u0, u1;
            u0.x = *reinterpret_cast<uint32_t*>(&h01);
            u0.y = *reinterpret_cast<uint32_t*>(&h23);
            u1.x = *reinterpret_cast<uint32_t*>(&h45);
            u1.y = *reinterpret_cast<uint32_t*>(&h67);
            *(uint2*)&Ph[sr * 72 + sc]     = u0;
            *(uint2*)&Ph[sr * 72 + sc + 4] = u1;
            float psum = ((p0 + p1) + (p2 + p3)) + ((p4 + p5) + (p6 + p7));
            psum += __shfl_xor_sync(0xffffffffu, psum, 1);
            psum += __shfl_xor_sync(0xffffffffu, psum, 2);
            l_r = l_r * alpha + psum;
            m_r = mnew;
            if ((t & 3) == 0) {
                alpha_s[sr] = alpha;
                if (kt == SEQ / 32 - 1) ls_s[sr] = 1.f / l_r;
            }
        }
        __syncthreads();   // P + alpha visible

        // ---- O rescale + PV (2 fp16 combos: P*Vh + P*Vl) ----
        {
            float a0 = alpha_s[mb + g], a1 = alpha_s[mb + g + 8];
#pragma unroll
            for (int j = 0; j < 4; j++) {
                o[j][0] *= a0; o[j][1] *= a0;
                o[j][2] *= a1; o[j][3] *= a1;
            }
#pragma unroll
            for (int ks = 0; ks < 2; ks++) {
                int ko = ks * 16;
                uint32_t pa[4];
                pa[0] = *(const uint32_t*)&Ph[(mb + g) * 72 + ko + 2 * tg];
                pa[1] = *(const uint32_t*)&Ph[(mb + g + 8) * 72 + ko + 2 * tg];
                pa[2] = *(const uint32_t*)&Ph[(mb + g) * 72 + ko + 8 + 2 * tg];
                pa[3] = *(const uint32_t*)&Ph[(mb + g + 8) * 72 + ko + 8 + 2 * tg];
#pragma unroll
                for (int j = 0; j < 4; j++) {
                    int n = wn * 32 + j * 8 + g;
                    uint32_t vb[2], vl[2];
                    vb[0] = *(const uint32_t*)&Vhs[b][n * 40 + ko + 2 * tg];
                    vb[1] = *(const uint32_t*)&Vhs[b][n * 40 + ko + 8 + 2 * tg];
                    vl[0] = *(const uint32_t*)&Vls[b][n * 40 + ko + 2 * tg];
                    vl[1] = *(const uint32_t*)&Vls[b][n * 40 + ko + 8 + 2 * tg];
                    MMA_F16(o[j], pa, vb);
                    MMA_F16(o[j], pa, vl);
                }
            }
        }
        // CRITICAL: all warps must finish reading Vhs[b]/Vls[b]/Ph before the
        // next iteration's cp.async prefetch overwrites buffer b.
        __syncthreads();
        b ^= 1;
    }

    // epilogue: ctx[(q0+r)][d*32+h]
    float inv0 = ls_s[mb + g], inv1 = ls_s[mb + g + 8];
#pragma unroll
    for (int j = 0; j < 4; j++) {
        int d0 = wn * 32 + j * 8 + 2 * tg;
        int r0 = q0 + mb + g, r1 = r0 + 8;
        g_ctx[(size_t)r0 * DMODEL + d0 * NHEADS + h]       = o[j][0] * inv0;
        g_ctx[(size_t)r0 * DMODEL + (d0 + 1) * NHEADS + h] = o[j][1] * inv0;
        g_ctx[(size_t)r1 * DMODEL + d0 * NHEADS + h]       = o[j][2] * inv1;
        g_ctx[(size_t)r1 * DMODEL + (d0 + 1) * NHEADS + h] = o[j][3] * inv1;
    }
}

// ===========================================================================
extern "C" void kernel_launch(void* const* d_in, const int* in_sizes, int n_in,
                              void* d_out, int out_size)
{
    (void)in_sizes; (void)n_in; (void)out_size;
    const float* X  = (const float*)d_in[0];
    const float* Wq = (const float*)d_in[1];
    const float* bq = (const float*)d_in[2];
    const float* Wk = (const float*)d_in[3];
    const float* bk = (const float*)d_in[4];
    const float* Wv = (const float*)d_in[5];
    const float* bv = (const float*)d_in[6];
    const float* Wo = (const float*)d_in[7];
    const float* bo = (const float*)d_in[8];
    float* out = (float*)d_out;

    const int SPLIT_GRID = (SEQ * DMODEL / 4) / 256;  // 4096
    split_kernel<<<SPLIT_GRID, 256>>>(X,  0);
    split_kernel<<<SPLIT_GRID, 256>>>(Wq, 1);
    split_kernel<<<SPLIT_GRID, 256>>>(Wk, 2);
    split_kernel<<<SPLIT_GRID, 256>>>(Wv, 3);
    split_kernel<<<SPLIT_GRID, 256>>>(Wo, 4);

    qkv_f16_gemm_kernel<<<dim3(16, 16, 3), 256, GEMM_SMEM>>>(bq, bk, bv);
    head_transpose_kernel<<<dim3(SEQ / 4, 3), 256>>>();
    vtrans_kernel<<<dim3(SEQ / 64, NHEADS), 256>>>();
    attn_kernel<<<dim3(SEQ / 64, NHEADS), 256>>>();
    split_kernel<<<SPLIT_GRID, 256>>>(nullptr, 5);
    o_f16_gemm_kernel<<<dim3(16, 16), 256, GEMM_SMEM>>>(bo, out);
}